// round 1
// baseline (speedup 1.0000x reference)
#include <cuda_runtime.h>
#include <math.h>

#define D 128
#define MAX_N_STU 100000
#define MAX_N_ITEM 20000

// ---------------- scratch (device globals; no allocation allowed) ------------
__device__ float g_agg_item[(size_t)MAX_N_ITEM * D];
__device__ float g_cnt_item[MAX_N_ITEM];
__device__ float g_agg_stu[(size_t)MAX_N_STU * D];
__device__ float g_cnt_stu[MAX_N_STU];
__device__ float g_P[(size_t)MAX_N_STU * D];
__device__ float g_Q[(size_t)MAX_N_STU * D];
__device__ float g_Hsum[(size_t)MAX_N_STU * D];
__device__ float g_cnt_p[MAX_N_STU];
__device__ float g_item_elu[(size_t)MAX_N_ITEM * D];
__device__ float g_stu_elu[(size_t)MAX_N_STU * D];
__device__ float g_stats[4 * D];  // [0:128) itemSum [128:256) itemSumSq [256:384) stuSum [384:512) stuSumSq

// ---------------- zero the accumulators --------------------------------------
__global__ void zero_all_kernel() {
    size_t i = blockIdx.x * (size_t)blockDim.x + threadIdx.x;
    size_t stride = (size_t)gridDim.x * blockDim.x;
    const size_t nItem = (size_t)MAX_N_ITEM * D;
    const size_t nStu = (size_t)MAX_N_STU * D;
    for (size_t x = i; x < nStu; x += stride) {
        g_agg_stu[x] = 0.f;
        g_Hsum[x] = 0.f;
        if (x < nItem) g_agg_item[x] = 0.f;
        if (x < MAX_N_STU) { g_cnt_stu[x] = 0.f; g_cnt_p[x] = 0.f; }
        if (x < MAX_N_ITEM) g_cnt_item[x] = 0.f;
        if (x < 4 * D) g_stats[x] = 0.f;
    }
}

// ---------------- edge kernels ------------------------------------------------
// One warp per edge; each lane moves one float4 (128 floats/row).
__device__ __forceinline__ void red_add_v4(float* p, float4 v) {
    asm volatile("red.global.add.v4.f32 [%0], {%1,%2,%3,%4};"
                 :: "l"(p), "f"(v.x), "f"(v.y), "f"(v.z), "f"(v.w) : "memory");
}

__global__ void edge_agg_kernel(const float* __restrict__ X,
                                const int* __restrict__ src,
                                const int* __restrict__ dst,
                                float* __restrict__ accum,
                                float* __restrict__ cnt, int E) {
    int w = (blockIdx.x * blockDim.x + threadIdx.x) >> 5;
    if (w >= E) return;
    int lane = threadIdx.x & 31;
    int s = src[w], d = dst[w];
    float4 v = ((const float4*)(X + (size_t)s * D))[lane];
    red_add_v4(accum + (size_t)d * D + lane * 4, v);
    if (lane == 0) atomicAdd(cnt + d, 1.0f);
}

__device__ __forceinline__ float elu1(float x) {
    return x > 0.f ? x : expm1f(x);
}

__global__ void edge_simple_kernel(const float* __restrict__ P,
                                   const float* __restrict__ Q,
                                   const int* __restrict__ src,
                                   const int* __restrict__ dst,
                                   const float* __restrict__ b1,
                                   float* __restrict__ Hsum,
                                   float* __restrict__ cnt, int E) {
    int w = (blockIdx.x * blockDim.x + threadIdx.x) >> 5;
    if (w >= E) return;
    int lane = threadIdx.x & 31;
    int s = src[w], d = dst[w];
    float4 ps = ((const float4*)(P + (size_t)s * D))[lane];
    float4 qs = ((const float4*)(Q + (size_t)s * D))[lane];
    float4 qd = ((const float4*)(Q + (size_t)d * D))[lane];
    float4 bb = ((const float4*)b1)[lane];
    float4 h;
    h.x = elu1(ps.x - qs.x + qd.x + bb.x);
    h.y = elu1(ps.y - qs.y + qd.y + bb.y);
    h.z = elu1(ps.z - qs.z + qd.z + bb.z);
    h.w = elu1(ps.w - qs.w + qd.w + bb.w);
    red_add_v4(Hsum + (size_t)d * D + lane * 4, h);
    if (lane == 0) atomicAdd(cnt + d, 1.0f);
}

// ---------------- GEMM building block (K = N = 128) ---------------------------
// 256 threads, 64-row tile. Warp ty handles rows ty*8..ty*8+7; lane tx handles
// cols tx*4..tx*4+3. smem: sW 64KB + sA 32KB (dynamic, 96KB total).
__device__ __forceinline__ void mm_accum(const float* __restrict__ A,
                                         const float* __restrict__ W,
                                         const float* __restrict__ cntScale,
                                         int M, int rowBase, float acc[8][4],
                                         float* sW, float* sA) {
    __syncthreads();  // previous consumer of smem done
    const float4* W4 = (const float4*)W;
    float4* sW4 = (float4*)sW;
    for (int i = threadIdx.x; i < 128 * 32; i += 256) sW4[i] = W4[i];
    float4* sA4 = (float4*)sA;
    for (int i = threadIdx.x; i < 64 * 32; i += 256) {
        int r = i >> 5, c = i & 31;
        int gr = rowBase + r;
        float4 v = make_float4(0.f, 0.f, 0.f, 0.f);
        if (gr < M) {
            v = ((const float4*)(A + (size_t)gr * D))[c];
            if (cntScale) {
                float inv = 1.f / fmaxf(cntScale[gr], 1.f);
                v.x *= inv; v.y *= inv; v.z *= inv; v.w *= inv;
            }
        }
        sA4[i] = v;
    }
    __syncthreads();
    int tx = threadIdx.x & 31, ty = threadIdx.x >> 5;
#pragma unroll 4
    for (int k = 0; k < 128; k += 4) {
        float4 w0 = ((const float4*)(sW + (k + 0) * 128))[tx];
        float4 w1 = ((const float4*)(sW + (k + 1) * 128))[tx];
        float4 w2 = ((const float4*)(sW + (k + 2) * 128))[tx];
        float4 w3 = ((const float4*)(sW + (k + 3) * 128))[tx];
#pragma unroll
        for (int r = 0; r < 8; r++) {
            float4 a = *((const float4*)(sA + (ty * 8 + r) * 128 + k));
            acc[r][0] += a.x * w0.x + a.y * w1.x + a.z * w2.x + a.w * w3.x;
            acc[r][1] += a.x * w0.y + a.y * w1.y + a.z * w2.y + a.w * w3.y;
            acc[r][2] += a.x * w0.z + a.y * w1.z + a.z * w2.z + a.w * w3.z;
            acc[r][3] += a.x * w0.w + a.y * w1.w + a.z * w2.w + a.w * w3.w;
        }
    }
}

__global__ __launch_bounds__(256) void gemm128_kernel(const float* __restrict__ A,
                                                      const float* __restrict__ W,
                                                      float* __restrict__ C, int M) {
    extern __shared__ float smem[];
    float* sW = smem;
    float* sA = smem + 128 * 128;
    float acc[8][4] = {};
    int rowBase = blockIdx.x * 64;
    mm_accum(A, W, nullptr, M, rowBase, acc, sW, sA);
    int tx = threadIdx.x & 31, ty = threadIdx.x >> 5;
#pragma unroll
    for (int r = 0; r < 8; r++) {
        int gr = rowBase + ty * 8 + r;
        if (gr < M)
            ((float4*)(C + (size_t)gr * D))[tx] =
                make_float4(acc[r][0], acc[r][1], acc[r][2], acc[r][3]);
    }
}

// Shared epilogue: elu, store to eluBuf, accumulate per-column sum/sumsq.
__device__ __forceinline__ void epilogue_elu_stats(float acc[8][4], int rowBase,
                                                   int M, float* __restrict__ eluBuf,
                                                   float* __restrict__ statSum,
                                                   float* __restrict__ statSS,
                                                   float* sRed) {
    int tx = threadIdx.x & 31, ty = threadIdx.x >> 5;
    float* shSum = sRed;
    float* shSS = sRed + 128;
    __syncthreads();
    if (threadIdx.x < 128) { shSum[threadIdx.x] = 0.f; shSS[threadIdx.x] = 0.f; }
    __syncthreads();
    float lsum[4] = {0.f, 0.f, 0.f, 0.f}, lss[4] = {0.f, 0.f, 0.f, 0.f};
#pragma unroll
    for (int r = 0; r < 8; r++) {
        int gr = rowBase + ty * 8 + r;
        if (gr < M) {
            float vv[4];
#pragma unroll
            for (int q = 0; q < 4; q++) {
                float e = elu1(acc[r][q]);
                vv[q] = e;
                lsum[q] += e;
                lss[q] += e * e;
            }
            ((float4*)(eluBuf + (size_t)gr * D))[tx] =
                make_float4(vv[0], vv[1], vv[2], vv[3]);
        }
    }
#pragma unroll
    for (int q = 0; q < 4; q++) {
        atomicAdd(shSum + tx * 4 + q, lsum[q]);
        atomicAdd(shSS + tx * 4 + q, lss[q]);
    }
    __syncthreads();
    if (threadIdx.x < 128) {
        atomicAdd(statSum + threadIdx.x, shSum[threadIdx.x]);
        atomicAdd(statSS + threadIdx.x, shSS[threadIdx.x]);
    }
}

// item_out = elu( mean_agg@Wl + x_item@Wr + b )
__global__ __launch_bounds__(256) void out_item_kernel(
    const float* __restrict__ aggI, const float* __restrict__ cntI,
    const float* __restrict__ x_item, const float* __restrict__ Wl,
    const float* __restrict__ Wr, const float* __restrict__ b,
    float* __restrict__ eluBuf, float* __restrict__ stats, int M) {
    extern __shared__ float smem[];
    float* sW = smem;
    float* sA = smem + 128 * 128;
    float acc[8][4] = {};
    int rowBase = blockIdx.x * 64;
    mm_accum(aggI, Wl, cntI, M, rowBase, acc, sW, sA);
    mm_accum(x_item, Wr, nullptr, M, rowBase, acc, sW, sA);
    int tx = threadIdx.x & 31;
#pragma unroll
    for (int r = 0; r < 8; r++)
#pragma unroll
        for (int q = 0; q < 4; q++) acc[r][q] += b[tx * 4 + q];
    epilogue_elu_stats(acc, rowBase, M, eluBuf, stats + 0, stats + 128, sA);
}

// stu_out = elu( 0.5*( aggS@Wl + x_stu@Wr + b_st + meanH@W2 + b2*[cnt>0] ) )
__global__ __launch_bounds__(256) void out_stu_kernel(
    const float* __restrict__ aggS, const float* __restrict__ cntS,
    const float* __restrict__ x_stu, const float* __restrict__ Hsum,
    const float* __restrict__ cntP, const float* __restrict__ Wl,
    const float* __restrict__ Wr, const float* __restrict__ W2,
    const float* __restrict__ b_st, const float* __restrict__ b2,
    float* __restrict__ eluBuf, float* __restrict__ stats, int M) {
    extern __shared__ float smem[];
    float* sW = smem;
    float* sA = smem + 128 * 128;
    float acc[8][4] = {};
    int rowBase = blockIdx.x * 64;
    mm_accum(aggS, Wl, cntS, M, rowBase, acc, sW, sA);
    mm_accum(x_stu, Wr, nullptr, M, rowBase, acc, sW, sA);
    mm_accum(Hsum, W2, cntP, M, rowBase, acc, sW, sA);
    int tx = threadIdx.x & 31, ty = threadIdx.x >> 5;
#pragma unroll
    for (int r = 0; r < 8; r++) {
        int gr = rowBase + ty * 8 + r;
        float hasP = (gr < M && cntP[gr] > 0.f) ? 1.f : 0.f;
#pragma unroll
        for (int q = 0; q < 4; q++)
            acc[r][q] = 0.5f * (acc[r][q] + b_st[tx * 4 + q] + hasP * b2[tx * 4 + q]);
    }
    epilogue_elu_stats(acc, rowBase, M, eluBuf, stats + 256, stats + 384, sA);
}

// ---------------- batch-norm finalize -----------------------------------------
__global__ void bn_final_kernel(const float* __restrict__ x,
                                const float* __restrict__ stats, int statOff,
                                const float* __restrict__ g,
                                const float* __restrict__ beta, int N,
                                float* __restrict__ out) {
    __shared__ float sScale[128], sShift[128];
    if (threadIdx.x < 128) {
        int j = threadIdx.x;
        float invN = 1.f / (float)N;
        float mu = stats[statOff + j] * invN;
        float var = fmaxf(stats[statOff + 128 + j] * invN - mu * mu, 0.f);
        float sc = g[j] * rsqrtf(var + 1e-5f);
        sScale[j] = sc;
        sShift[j] = beta[j] - mu * sc;
    }
    __syncthreads();
    size_t total = (size_t)N * 32;  // float4 count
    size_t i = blockIdx.x * (size_t)blockDim.x + threadIdx.x;
    size_t stride = (size_t)gridDim.x * blockDim.x;
    const float4* x4 = (const float4*)x;
    float4* o4 = (float4*)out;
    for (; i < total; i += stride) {
        int j = ((int)i & 31) * 4;
        float4 v = x4[i];
        v.x = v.x * sScale[j + 0] + sShift[j + 0];
        v.y = v.y * sScale[j + 1] + sShift[j + 1];
        v.z = v.z * sScale[j + 2] + sShift[j + 2];
        v.w = v.w * sScale[j + 3] + sShift[j + 3];
        o4[i] = v;
    }
}

// ---------------- launch -------------------------------------------------------
extern "C" void kernel_launch(void* const* d_in, const int* in_sizes, int n_in,
                              void* d_out, int out_size) {
    const float* x_student = (const float*)d_in[0];
    const float* x_item = (const float*)d_in[1];
    const int* responds_src = (const int*)d_in[2];
    const int* responds_dst = (const int*)d_in[3];
    const int* preceeds_src = (const int*)d_in[4];
    const int* preceeds_dst = (const int*)d_in[5];
    const float* sage_it_Wl = (const float*)d_in[6];
    const float* sage_it_Wr = (const float*)d_in[7];
    const float* sage_it_b = (const float*)d_in[8];
    const float* sage_st_Wl = (const float*)d_in[9];
    const float* sage_st_Wr = (const float*)d_in[10];
    const float* sage_st_b = (const float*)d_in[11];
    const float* sc_W1 = (const float*)d_in[12];
    const float* sc_b1 = (const float*)d_in[13];
    const float* sc_W2 = (const float*)d_in[14];
    const float* sc_b2 = (const float*)d_in[15];
    const float* bn_item_g = (const float*)d_in[16];
    const float* bn_item_b = (const float*)d_in[17];
    const float* bn_stu_g = (const float*)d_in[18];
    const float* bn_stu_b = (const float*)d_in[19];

    int n_stu = in_sizes[0] / D;
    int n_item = in_sizes[1] / D;
    int e_r = in_sizes[2];
    int e_p = in_sizes[4];

    const int DYN_SMEM = (128 * 128 + 64 * 128) * 4;  // 96 KB
    cudaFuncSetAttribute(gemm128_kernel, cudaFuncAttributeMaxDynamicSharedMemorySize, DYN_SMEM);
    cudaFuncSetAttribute(out_item_kernel, cudaFuncAttributeMaxDynamicSharedMemorySize, DYN_SMEM);
    cudaFuncSetAttribute(out_stu_kernel, cudaFuncAttributeMaxDynamicSharedMemorySize, DYN_SMEM);

    void *pAggI, *pCntI, *pAggS, *pCntS, *pP, *pQ, *pH, *pCntP, *pItemE, *pStuE, *pStats;
    cudaGetSymbolAddress(&pAggI, g_agg_item);
    cudaGetSymbolAddress(&pCntI, g_cnt_item);
    cudaGetSymbolAddress(&pAggS, g_agg_stu);
    cudaGetSymbolAddress(&pCntS, g_cnt_stu);
    cudaGetSymbolAddress(&pP, g_P);
    cudaGetSymbolAddress(&pQ, g_Q);
    cudaGetSymbolAddress(&pH, g_Hsum);
    cudaGetSymbolAddress(&pCntP, g_cnt_p);
    cudaGetSymbolAddress(&pItemE, g_item_elu);
    cudaGetSymbolAddress(&pStuE, g_stu_elu);
    cudaGetSymbolAddress(&pStats, g_stats);

    zero_all_kernel<<<2048, 256>>>();

    // P = x_student @ W1[:128,:], Q = x_student @ W1[128:,:]
    int gb_stu = (n_stu + 63) / 64;
    gemm128_kernel<<<gb_stu, 256, DYN_SMEM>>>(x_student, sc_W1, (float*)pP, n_stu);
    gemm128_kernel<<<gb_stu, 256, DYN_SMEM>>>(x_student, sc_W1 + 128 * D, (float*)pQ, n_stu);

    // responds: student -> item aggregation (segment sum + count)
    edge_agg_kernel<<<(e_r + 7) / 8, 256>>>(x_student, responds_src, responds_dst,
                                            (float*)pAggI, (float*)pCntI, e_r);
    // rev_responds: item -> student aggregation
    edge_agg_kernel<<<(e_r + 7) / 8, 256>>>(x_item, responds_dst, responds_src,
                                            (float*)pAggS, (float*)pCntS, e_r);
    // preceeds: per-edge ELU of P[s]-Q[s]+Q[d]+b1, scattered to Hsum[d]
    edge_simple_kernel<<<(e_p + 7) / 8, 256>>>((const float*)pP, (const float*)pQ,
                                               preceeds_src, preceeds_dst, sc_b1,
                                               (float*)pH, (float*)pCntP, e_p);

    out_item_kernel<<<(n_item + 63) / 64, 256, DYN_SMEM>>>(
        (const float*)pAggI, (const float*)pCntI, x_item, sage_it_Wl, sage_it_Wr,
        sage_it_b, (float*)pItemE, (float*)pStats, n_item);
    out_stu_kernel<<<gb_stu, 256, DYN_SMEM>>>(
        (const float*)pAggS, (const float*)pCntS, x_student, (const float*)pH,
        (const float*)pCntP, sage_st_Wl, sage_st_Wr, sc_W2, sage_st_b, sc_b2,
        (float*)pStuE, (float*)pStats, n_stu);

    float* out = (float*)d_out;
    bn_final_kernel<<<1024, 256>>>((const float*)pItemE, (const float*)pStats, 0,
                                   bn_item_g, bn_item_b, n_item, out);
    bn_final_kernel<<<2048, 256>>>((const float*)pStuE, (const float*)pStats, 256,
                                   bn_stu_g, bn_stu_b, n_stu,
                                   out + (size_t)n_item * D);
}

// round 2
// speedup vs baseline: 1.0431x; 1.0431x over previous
#include <cuda_runtime.h>
#include <math.h>

#define D 128
#define MAX_N_STU 100000
#define MAX_N_ITEM 20000
#define SA_STRIDE 132  // 128 + 4 pad: conflict-free fragment LDS

// ---------------- scratch (device globals; no allocation allowed) ------------
__device__ float g_agg_item[(size_t)MAX_N_ITEM * D];
__device__ float g_cnt_item[MAX_N_ITEM];
__device__ float g_agg_stu[(size_t)MAX_N_STU * D];
__device__ float g_cnt_stu[MAX_N_STU];
__device__ float g_P[(size_t)MAX_N_STU * D];
__device__ float g_Q[(size_t)MAX_N_STU * D];
__device__ float g_Hsum[(size_t)MAX_N_STU * D];
__device__ float g_cnt_p[MAX_N_STU];
__device__ float g_stats[4 * D];  // itemSum | itemSS | stuSum | stuSS

// ---------------- zero kernel -------------------------------------------------
__global__ void zero_all_kernel() {
    size_t i = blockIdx.x * (size_t)blockDim.x + threadIdx.x;
    size_t stride = (size_t)gridDim.x * blockDim.x;
    const size_t nItem = (size_t)MAX_N_ITEM * D;
    const size_t nStu = (size_t)MAX_N_STU * D;
    for (size_t x = i; x < nStu; x += stride) {
        g_agg_stu[x] = 0.f;
        g_Hsum[x] = 0.f;
        if (x < nItem) g_agg_item[x] = 0.f;
        if (x < MAX_N_STU) { g_cnt_stu[x] = 0.f; g_cnt_p[x] = 0.f; }
        if (x < MAX_N_ITEM) g_cnt_item[x] = 0.f;
        if (x < 4 * D) g_stats[x] = 0.f;
    }
}

// ---------------- edge kernels ------------------------------------------------
__device__ __forceinline__ void red_add_v4(float* p, float4 v) {
    asm volatile("red.global.add.v4.f32 [%0], {%1,%2,%3,%4};"
                 :: "l"(p), "f"(v.x), "f"(v.y), "f"(v.z), "f"(v.w) : "memory");
}

__global__ void edge_agg_kernel(const float* __restrict__ X,
                                const int* __restrict__ src,
                                const int* __restrict__ dst,
                                float* __restrict__ accum,
                                float* __restrict__ cnt, int E) {
    int w = (blockIdx.x * blockDim.x + threadIdx.x) >> 5;
    if (w >= E) return;
    int lane = threadIdx.x & 31;
    int s = src[w], d = dst[w];
    float4 v = ((const float4*)(X + (size_t)s * D))[lane];
    red_add_v4(accum + (size_t)d * D + lane * 4, v);
    if (lane == 0) atomicAdd(cnt + d, 1.0f);
}

__device__ __forceinline__ float elu1(float x) {
    return x > 0.f ? x : expm1f(x);
}

__global__ void edge_simple_kernel(const float* __restrict__ P,
                                   const float* __restrict__ Q,
                                   const int* __restrict__ src,
                                   const int* __restrict__ dst,
                                   const float* __restrict__ b1,
                                   float* __restrict__ Hsum,
                                   float* __restrict__ cnt, int E) {
    int w = (blockIdx.x * blockDim.x + threadIdx.x) >> 5;
    if (w >= E) return;
    int lane = threadIdx.x & 31;
    int s = src[w], d = dst[w];
    float4 ps = ((const float4*)(P + (size_t)s * D))[lane];
    float4 qs = ((const float4*)(Q + (size_t)s * D))[lane];
    float4 qd = ((const float4*)(Q + (size_t)d * D))[lane];
    float4 bb = ((const float4*)b1)[lane];
    float4 h;
    h.x = elu1(ps.x - qs.x + qd.x + bb.x);
    h.y = elu1(ps.y - qs.y + qd.y + bb.y);
    h.z = elu1(ps.z - qs.z + qd.z + bb.z);
    h.w = elu1(ps.w - qs.w + qd.w + bb.w);
    red_add_v4(Hsum + (size_t)d * D + lane * 4, h);
    if (lane == 0) atomicAdd(cnt + d, 1.0f);
}

// ---------------- tensor-core GEMM pieces (tf32 mma.sync) ---------------------
__device__ __forceinline__ unsigned f2tf(float x) {
    unsigned r;
    asm("cvt.rna.tf32.f32 %0, %1;" : "=r"(r) : "f"(x));
    return r;
}

// Stage A tile: 128 rows x 128 K, optional mean-scale by cnt, tf32 rounding.
__device__ __forceinline__ void stage_A(const float* __restrict__ A,
                                        const float* __restrict__ cnt, int M,
                                        int rowBase, unsigned* sA) {
    for (int i = threadIdx.x; i < 128 * 32; i += 256) {
        int r = i >> 5, c4 = (i & 31) * 4;
        int gr = rowBase + r;
        float4 v = make_float4(0.f, 0.f, 0.f, 0.f);
        if (gr < M) {
            v = ((const float4*)(A + (size_t)gr * D))[c4 >> 2];
            if (cnt) {
                float inv = 1.f / fmaxf(cnt[gr], 1.f);
                v.x *= inv; v.y *= inv; v.z *= inv; v.w *= inv;
            }
        }
        unsigned* p = sA + r * SA_STRIDE + c4;
        p[0] = f2tf(v.x); p[1] = f2tf(v.y); p[2] = f2tf(v.z); p[3] = f2tf(v.w);
    }
}

// Stage W transposed: sW[n*SA_STRIDE + k] = tf32(W[k][n]).
// Warp lanes take consecutive k at fixed n4 -> conflict-free STS.
__device__ __forceinline__ void stage_Wt(const float* __restrict__ W, unsigned* sW) {
    for (int i = threadIdx.x; i < 128 * 32; i += 256) {
        int k = i & 127, n4 = i >> 7;
        float4 v = ((const float4*)(W + (size_t)k * D))[n4];
        sW[(n4 * 4 + 0) * SA_STRIDE + k] = f2tf(v.x);
        sW[(n4 * 4 + 1) * SA_STRIDE + k] = f2tf(v.y);
        sW[(n4 * 4 + 2) * SA_STRIDE + k] = f2tf(v.z);
        sW[(n4 * 4 + 3) * SA_STRIDE + k] = f2tf(v.w);
    }
}

// Warp computes its 16 rows x 128 cols. acc[j][0..3] = m16n8 tile j.
__device__ __forceinline__ void mm_tc(const unsigned* sA, const unsigned* sW,
                                      float acc[16][4]) {
    int lane = threadIdx.x & 31, w = threadIdx.x >> 5;
    int g = lane >> 2, t = lane & 3;
    const unsigned* Abase = sA + (w * 16 + g) * SA_STRIDE + t;
#pragma unroll
    for (int k0 = 0; k0 < 128; k0 += 8) {
        unsigned a0 = Abase[k0];
        unsigned a1 = Abase[8 * SA_STRIDE + k0];
        unsigned a2 = Abase[k0 + 4];
        unsigned a3 = Abase[8 * SA_STRIDE + k0 + 4];
        const unsigned* Bk = sW + g * SA_STRIDE + k0 + t;
#pragma unroll
        for (int j = 0; j < 16; j++) {
            unsigned b0 = Bk[8 * j * SA_STRIDE];
            unsigned b1 = Bk[8 * j * SA_STRIDE + 4];
            asm volatile(
                "mma.sync.aligned.m16n8k8.row.col.f32.tf32.tf32.f32 "
                "{%0,%1,%2,%3},{%4,%5,%6,%7},{%8,%9},{%0,%1,%2,%3};"
                : "+f"(acc[j][0]), "+f"(acc[j][1]), "+f"(acc[j][2]), "+f"(acc[j][3])
                : "r"(a0), "r"(a1), "r"(a2), "r"(a3), "r"(b0), "r"(b1));
        }
    }
}

// P = x@W1[:128], Q = x@W1[128:]; shares the staged A tile.
__global__ __launch_bounds__(256) void gemm_pq_tc(const float* __restrict__ x,
                                                  const float* __restrict__ W1,
                                                  float* __restrict__ P,
                                                  float* __restrict__ Q, int M) {
    extern __shared__ unsigned smem_u[];
    unsigned* sA = smem_u;
    unsigned* sW = smem_u + 128 * SA_STRIDE;
    int rowBase = blockIdx.x * 128;
    int lane = threadIdx.x & 31, w = threadIdx.x >> 5;
    int g = lane >> 2, t = lane & 3;
    int r0 = rowBase + w * 16 + g, r1 = r0 + 8;

    stage_A(x, nullptr, M, rowBase, sA);
    stage_Wt(W1, sW);
    __syncthreads();
    {
        float acc[16][4] = {};
        mm_tc(sA, sW, acc);
#pragma unroll
        for (int j = 0; j < 16; j++) {
            int c = 8 * j + 2 * t;
            if (r0 < M) *(float2*)(P + (size_t)r0 * D + c) = make_float2(acc[j][0], acc[j][1]);
            if (r1 < M) *(float2*)(P + (size_t)r1 * D + c) = make_float2(acc[j][2], acc[j][3]);
        }
    }
    __syncthreads();
    stage_Wt(W1 + 128 * D, sW);
    __syncthreads();
    {
        float acc[16][4] = {};
        mm_tc(sA, sW, acc);
#pragma unroll
        for (int j = 0; j < 16; j++) {
            int c = 8 * j + 2 * t;
            if (r0 < M) *(float2*)(Q + (size_t)r0 * D + c) = make_float2(acc[j][0], acc[j][1]);
            if (r1 < M) *(float2*)(Q + (size_t)r1 * D + c) = make_float2(acc[j][2], acc[j][3]);
        }
    }
}

// item_out_pre_bn = elu( mean_agg@Wl + x_item@Wr + b ) -> out
__global__ __launch_bounds__(256) void out_item_tc(
    const float* __restrict__ aggI, const float* __restrict__ cntI,
    const float* __restrict__ x_item, const float* __restrict__ Wl,
    const float* __restrict__ Wr, const float* __restrict__ b,
    float* __restrict__ out, int M) {
    extern __shared__ unsigned smem_u[];
    unsigned* sA = smem_u;
    unsigned* sW = smem_u + 128 * SA_STRIDE;
    int rowBase = blockIdx.x * 128;
    float acc[16][4] = {};

    stage_A(aggI, cntI, M, rowBase, sA);
    stage_Wt(Wl, sW);
    __syncthreads();
    mm_tc(sA, sW, acc);
    __syncthreads();
    stage_A(x_item, nullptr, M, rowBase, sA);
    stage_Wt(Wr, sW);
    __syncthreads();
    mm_tc(sA, sW, acc);

    int lane = threadIdx.x & 31, w = threadIdx.x >> 5;
    int g = lane >> 2, t = lane & 3;
    int r0 = rowBase + w * 16 + g, r1 = r0 + 8;
#pragma unroll
    for (int j = 0; j < 16; j++) {
        int c = 8 * j + 2 * t;
        float b0v = b[c], b1v = b[c + 1];
        if (r0 < M)
            *(float2*)(out + (size_t)r0 * D + c) =
                make_float2(elu1(acc[j][0] + b0v), elu1(acc[j][1] + b1v));
        if (r1 < M)
            *(float2*)(out + (size_t)r1 * D + c) =
                make_float2(elu1(acc[j][2] + b0v), elu1(acc[j][3] + b1v));
    }
}

// stu_out_pre_bn = elu( 0.5*( aggS@Wl + x@Wr + b_st + meanH@W2 + [cntP>0]*b2 ) )
__global__ __launch_bounds__(256) void out_stu_tc(
    const float* __restrict__ aggS, const float* __restrict__ cntS,
    const float* __restrict__ x_stu, const float* __restrict__ Hsum,
    const float* __restrict__ cntP, const float* __restrict__ Wl,
    const float* __restrict__ Wr, const float* __restrict__ W2,
    const float* __restrict__ b_st, const float* __restrict__ b2,
    float* __restrict__ out, int M) {
    extern __shared__ unsigned smem_u[];
    unsigned* sA = smem_u;
    unsigned* sW = smem_u + 128 * SA_STRIDE;
    int rowBase = blockIdx.x * 128;
    float acc[16][4] = {};

    stage_A(aggS, cntS, M, rowBase, sA);
    stage_Wt(Wl, sW);
    __syncthreads();
    mm_tc(sA, sW, acc);
    __syncthreads();
    stage_A(x_stu, nullptr, M, rowBase, sA);
    stage_Wt(Wr, sW);
    __syncthreads();
    mm_tc(sA, sW, acc);
    __syncthreads();
    stage_A(Hsum, cntP, M, rowBase, sA);
    stage_Wt(W2, sW);
    __syncthreads();
    mm_tc(sA, sW, acc);

    int lane = threadIdx.x & 31, w = threadIdx.x >> 5;
    int g = lane >> 2, t = lane & 3;
    int r0 = rowBase + w * 16 + g, r1 = r0 + 8;
    float hasP0 = (r0 < M && cntP[r0] > 0.f) ? 1.f : 0.f;
    float hasP1 = (r1 < M && cntP[r1] > 0.f) ? 1.f : 0.f;
#pragma unroll
    for (int j = 0; j < 16; j++) {
        int c = 8 * j + 2 * t;
        float bs0 = b_st[c], bs1 = b_st[c + 1];
        float b20 = b2[c], b21 = b2[c + 1];
        if (r0 < M)
            *(float2*)(out + (size_t)r0 * D + c) = make_float2(
                elu1(0.5f * (acc[j][0] + bs0 + hasP0 * b20)),
                elu1(0.5f * (acc[j][1] + bs1 + hasP0 * b21)));
        if (r1 < M)
            *(float2*)(out + (size_t)r1 * D + c) = make_float2(
                elu1(0.5f * (acc[j][2] + bs0 + hasP1 * b20)),
                elu1(0.5f * (acc[j][3] + bs1 + hasP1 * b21)));
    }
}

// ---------------- BN stats + finalize -----------------------------------------
__global__ void stats_kernel(const float* __restrict__ x, int N,
                             float* __restrict__ statSum,
                             float* __restrict__ statSS) {
    __shared__ float sSum[128], sSS[128];
    if (threadIdx.x < 128) { sSum[threadIdx.x] = 0.f; sSS[threadIdx.x] = 0.f; }
    __syncthreads();
    float ls[4] = {0.f, 0.f, 0.f, 0.f}, lss[4] = {0.f, 0.f, 0.f, 0.f};
    size_t total = (size_t)N * 32;
    size_t stride = (size_t)gridDim.x * blockDim.x;  // multiple of 32
    const float4* x4 = (const float4*)x;
    for (size_t i = blockIdx.x * (size_t)blockDim.x + threadIdx.x; i < total; i += stride) {
        float4 v = x4[i];
        ls[0] += v.x; lss[0] += v.x * v.x;
        ls[1] += v.y; lss[1] += v.y * v.y;
        ls[2] += v.z; lss[2] += v.z * v.z;
        ls[3] += v.w; lss[3] += v.w * v.w;
    }
    int c4 = (threadIdx.x & 31) * 4;
#pragma unroll
    for (int q = 0; q < 4; q++) {
        atomicAdd(sSum + c4 + q, ls[q]);
        atomicAdd(sSS + c4 + q, lss[q]);
    }
    __syncthreads();
    if (threadIdx.x < 128) {
        atomicAdd(statSum + threadIdx.x, sSum[threadIdx.x]);
        atomicAdd(statSS + threadIdx.x, sSS[threadIdx.x]);
    }
}

__global__ void bn_final_kernel(float* __restrict__ x,
                                const float* __restrict__ stats, int statOff,
                                const float* __restrict__ g,
                                const float* __restrict__ beta, int N) {
    __shared__ float sScale[128], sShift[128];
    if (threadIdx.x < 128) {
        int j = threadIdx.x;
        float invN = 1.f / (float)N;
        float mu = stats[statOff + j] * invN;
        float var = fmaxf(stats[statOff + 128 + j] * invN - mu * mu, 0.f);
        float sc = g[j] * rsqrtf(var + 1e-5f);
        sScale[j] = sc;
        sShift[j] = beta[j] - mu * sc;
    }
    __syncthreads();
    size_t total = (size_t)N * 32;
    size_t i = blockIdx.x * (size_t)blockDim.x + threadIdx.x;
    size_t stride = (size_t)gridDim.x * blockDim.x;
    float4* x4 = (float4*)x;
    for (; i < total; i += stride) {
        int j = ((int)i & 31) * 4;
        float4 v = x4[i];
        v.x = v.x * sScale[j + 0] + sShift[j + 0];
        v.y = v.y * sScale[j + 1] + sShift[j + 1];
        v.z = v.z * sScale[j + 2] + sShift[j + 2];
        v.w = v.w * sScale[j + 3] + sShift[j + 3];
        x4[i] = v;
    }
}

// ---------------- launch -------------------------------------------------------
extern "C" void kernel_launch(void* const* d_in, const int* in_sizes, int n_in,
                              void* d_out, int out_size) {
    const float* x_student = (const float*)d_in[0];
    const float* x_item = (const float*)d_in[1];
    const int* responds_src = (const int*)d_in[2];
    const int* responds_dst = (const int*)d_in[3];
    const int* preceeds_src = (const int*)d_in[4];
    const int* preceeds_dst = (const int*)d_in[5];
    const float* sage_it_Wl = (const float*)d_in[6];
    const float* sage_it_Wr = (const float*)d_in[7];
    const float* sage_it_b = (const float*)d_in[8];
    const float* sage_st_Wl = (const float*)d_in[9];
    const float* sage_st_Wr = (const float*)d_in[10];
    const float* sage_st_b = (const float*)d_in[11];
    const float* sc_W1 = (const float*)d_in[12];
    const float* sc_b1 = (const float*)d_in[13];
    const float* sc_W2 = (const float*)d_in[14];
    const float* sc_b2 = (const float*)d_in[15];
    const float* bn_item_g = (const float*)d_in[16];
    const float* bn_item_b = (const float*)d_in[17];
    const float* bn_stu_g = (const float*)d_in[18];
    const float* bn_stu_b = (const float*)d_in[19];

    int n_stu = in_sizes[0] / D;
    int n_item = in_sizes[1] / D;
    int e_r = in_sizes[2];
    int e_p = in_sizes[4];

    const int DYN_SMEM = 2 * 128 * SA_STRIDE * 4;  // ~132 KB
    cudaFuncSetAttribute(gemm_pq_tc, cudaFuncAttributeMaxDynamicSharedMemorySize, DYN_SMEM);
    cudaFuncSetAttribute(out_item_tc, cudaFuncAttributeMaxDynamicSharedMemorySize, DYN_SMEM);
    cudaFuncSetAttribute(out_stu_tc, cudaFuncAttributeMaxDynamicSharedMemorySize, DYN_SMEM);

    void *pAggI, *pCntI, *pAggS, *pCntS, *pP, *pQ, *pH, *pCntP, *pStats;
    cudaGetSymbolAddress(&pAggI, g_agg_item);
    cudaGetSymbolAddress(&pCntI, g_cnt_item);
    cudaGetSymbolAddress(&pAggS, g_agg_stu);
    cudaGetSymbolAddress(&pCntS, g_cnt_stu);
    cudaGetSymbolAddress(&pP, g_P);
    cudaGetSymbolAddress(&pQ, g_Q);
    cudaGetSymbolAddress(&pH, g_Hsum);
    cudaGetSymbolAddress(&pCntP, g_cnt_p);
    cudaGetSymbolAddress(&pStats, g_stats);

    float* out = (float*)d_out;
    float* out_item = out;
    float* out_stu = out + (size_t)n_item * D;

    zero_all_kernel<<<2048, 256>>>();

    int gb_stu = (n_stu + 127) / 128;
    int gb_item = (n_item + 127) / 128;

    // P/Q projections for SimpleConv (share A tile)
    gemm_pq_tc<<<gb_stu, 256, DYN_SMEM>>>(x_student, sc_W1, (float*)pP, (float*)pQ, n_stu);

    // edge aggregations
    edge_agg_kernel<<<(e_r + 7) / 8, 256>>>(x_student, responds_src, responds_dst,
                                            (float*)pAggI, (float*)pCntI, e_r);
    edge_agg_kernel<<<(e_r + 7) / 8, 256>>>(x_item, responds_dst, responds_src,
                                            (float*)pAggS, (float*)pCntS, e_r);
    edge_simple_kernel<<<(e_p + 7) / 8, 256>>>((const float*)pP, (const float*)pQ,
                                               preceeds_src, preceeds_dst, sc_b1,
                                               (float*)pH, (float*)pCntP, e_p);

    // fused output GEMMs (elu written straight into d_out)
    out_item_tc<<<gb_item, 256, DYN_SMEM>>>((const float*)pAggI, (const float*)pCntI,
                                            x_item, sage_it_Wl, sage_it_Wr, sage_it_b,
                                            out_item, n_item);
    out_stu_tc<<<gb_stu, 256, DYN_SMEM>>>((const float*)pAggS, (const float*)pCntS,
                                          x_student, (const float*)pH, (const float*)pCntP,
                                          sage_st_Wl, sage_st_Wr, sc_W2, sage_st_b, sc_b2,
                                          out_stu, n_stu);

    // batch-norm: stats over d_out, then normalize in place
    float* stats = (float*)pStats;
    stats_kernel<<<512, 256>>>(out_item, n_item, stats + 0, stats + 128);
    stats_kernel<<<2048, 256>>>(out_stu, n_stu, stats + 256, stats + 384);
    bn_final_kernel<<<512, 256>>>(out_item, stats, 0, bn_item_g, bn_item_b, n_item);
    bn_final_kernel<<<2048, 256>>>(out_stu, stats, 256, bn_stu_g, bn_stu_b, n_stu);
}